// round 2
// baseline (speedup 1.0000x reference)
#include <cuda_runtime.h>
#include <cstdint>

typedef unsigned long long ull;

constexpr int Bn = 128;
constexpr int Tn = 1024;
constexpr int In = 256;
constexpr int Hn = 512;

__device__ __forceinline__ ull pack2f(float x, float y) {
    ull r; asm("mov.b64 %0, {%1, %2};" : "=l"(r) : "f"(x), "f"(y)); return r;
}
__device__ __forceinline__ float2 unpack2f(ull v) {
    float2 r; asm("mov.b64 {%0, %1}, %2;" : "=f"(r.x), "=f"(r.y) : "l"(v)); return r;
}
__device__ __forceinline__ ull splat2f(float x) {
    ull r; asm("mov.b64 %0, {%1, %1};" : "=l"(r) : "f"(x)); return r;
}
__device__ __forceinline__ void ffma2(ull& a, ull x, ull y) {
    asm("fma.rn.f32x2 %0, %1, %2, %0;" : "+l"(a) : "l"(x), "l"(y));
}
__device__ __forceinline__ float sigmoidf_fast(float z) {
    return __fdividef(1.0f, 1.0f + __expf(-z));
}
__device__ __forceinline__ uint32_t smem_u32(const void* p) {
    return (uint32_t)__cvta_generic_to_shared(p);
}

// ---------------------------------------------------------------------------
// Kernel 1: igates[m][n] = sum_k X[m][k] * Wi[n][k] + bi[n]   (written to d_out)
//   64x64 tile, BK=32, transposed smem tiles [k][m]/[k][n] so the inner loop
//   uses vector LDS + packed fma.rn.f32x2 (half the FFMA issue of scalar).
// ---------------------------------------------------------------------------
__global__ __launch_bounds__(256) void igates_kernel(
    const float* __restrict__ X,
    const float* __restrict__ Wi,
    const float* __restrict__ bi,
    float* __restrict__ out)
{
    __shared__ __align__(16) float Xs[32][68];   // [k][m], pad keeps 16B row align
    __shared__ __align__(16) float Ws[32][68];   // [k][n]

    const int tid = threadIdx.x;
    const int tx = tid & 15;       // n micro-tile (0..15)
    const int ty = tid >> 4;       // m micro-tile (0..15)
    const int m0 = blockIdx.y * 64;
    const int n0 = blockIdx.x * 64;

    ull acc[4][2] = {};            // [m-sub][n-pair] packed f32x2 accumulators

    for (int k0 = 0; k0 < In; k0 += 32) {
        #pragma unroll
        for (int hh = 0; hh < 2; hh++) {
            int idx = tid + 256 * hh;     // 0..511
            int r   = idx >> 3;           // 0..63 (m or n)
            int c4  = idx & 7;            // k group of 4
            float4 v = *(const float4*)(X + (size_t)(m0 + r) * In + k0 + c4 * 4);
            Xs[c4*4+0][r] = v.x; Xs[c4*4+1][r] = v.y;
            Xs[c4*4+2][r] = v.z; Xs[c4*4+3][r] = v.w;
            float4 w = *(const float4*)(Wi + (size_t)(n0 + r) * In + k0 + c4 * 4);
            Ws[c4*4+0][r] = w.x; Ws[c4*4+1][r] = w.y;
            Ws[c4*4+2][r] = w.z; Ws[c4*4+3][r] = w.w;
        }
        __syncthreads();

        #pragma unroll
        for (int k = 0; k < 32; k++) {
            float4 a4 = *(const float4*)(&Xs[k][ty * 4]);
            const ull* b2 = (const ull*)(&Ws[k][tx * 4]);   // (b0,b1),(b2,b3)
            ull bp0 = b2[0], bp1 = b2[1];
            ull s0 = splat2f(a4.x), s1 = splat2f(a4.y),
                s2 = splat2f(a4.z), s3 = splat2f(a4.w);
            ffma2(acc[0][0], s0, bp0); ffma2(acc[0][1], s0, bp1);
            ffma2(acc[1][0], s1, bp0); ffma2(acc[1][1], s1, bp1);
            ffma2(acc[2][0], s2, bp0); ffma2(acc[2][1], s2, bp1);
            ffma2(acc[3][0], s3, bp0); ffma2(acc[3][1], s3, bp1);
        }
        __syncthreads();
    }

    float4 bv = *(const float4*)(bi + n0 + tx * 4);
    #pragma unroll
    for (int i = 0; i < 4; i++) {
        float2 lo = unpack2f(acc[i][0]);
        float2 hi = unpack2f(acc[i][1]);
        float4 o = make_float4(lo.x + bv.x, lo.y + bv.y, hi.x + bv.z, hi.y + bv.w);
        *(float4*)(out + (size_t)(m0 + ty*4 + i) * Hn + n0 + tx * 4) = o;
    }
}

// ---------------------------------------------------------------------------
// Kernel 2: persistent clustered recurrence with DSMEM h-exchange.
//   16 independent clusters x 8 CTAs. Cluster g owns batch rows [8g, 8g+8);
//   CTA c owns output columns [64c, 64c+64). h lives in a double-buffered
//   shared array hp[2][4][512] (packed row-pairs). Each step: compute the
//   [8 x 64] slice from hp[cur], then PUSH the new values into hp[cur^1] of
//   ALL 8 cluster CTAs via mapa + st.shared::cluster (no L2 round trip),
//   then one cluster barrier (release/acquire orders the DSMEM stores).
//   Wh slice stays in registers (128 regs/thread). Inner loop: LDS.128 of
//   packed h pairs + fma.rn.f32x2.
// ---------------------------------------------------------------------------
__global__ __launch_bounds__(256, 1) __cluster_dims__(8, 1, 1)
void rnn_kernel(
    float* __restrict__ out,
    const float* __restrict__ hidden,
    const float* __restrict__ Wh,
    const float* __restrict__ bh)
{
    __shared__ __align__(16) ull hp[2][4][512];   // [buf][row-pair][column]
    __shared__ __align__(16) ull part[4][4][64];  // [k-slice][row-pair][jj]

    const int tid   = threadIdx.x;
    const int jj    = tid & 63;
    const int rq    = tid >> 6;               // 0..3: k-slice in compute, row-pair in epilogue
    const int crank = blockIdx.x & 7;         // rank within 1-D cluster
    const int gbase = (blockIdx.x >> 3) * 8;  // batch base of this cluster
    const int j     = crank * 64 + jj;        // global output column
    const float bhj = bh[j];
    const int b0    = gbase + 2 * rq;

    float* __restrict__ hl = out + (size_t)Bn * Tn * Hn;   // h_last region

    // Wh slice in registers: Wh[j][rq*128 .. +127]
    float4 W4[32];
    {
        const float4* wp = (const float4*)(Wh + (size_t)j * Hn + rq * 128);
        #pragma unroll
        for (int u = 0; u < 32; u++) W4[u] = wp[u];
    }

    // Precompute DSMEM push addresses for both buffers x 8 ranks
    uint32_t ra[2][8];
    {
        uint32_t l0 = smem_u32(&hp[0][rq][j]);
        uint32_t l1 = smem_u32(&hp[1][rq][j]);
        #pragma unroll
        for (int r = 0; r < 8; r++) {
            asm("mapa.shared::cluster.u32 %0, %1, %2;" : "=r"(ra[0][r]) : "r"(l0), "r"(r));
            asm("mapa.shared::cluster.u32 %0, %1, %2;" : "=r"(ra[1][r]) : "r"(l1), "r"(r));
        }
    }

    // Stage initial hidden state into hp[0] (own smem only; rows are local)
    for (int i = tid; i < 2048; i += 256) {
        int rp = i >> 9, k = i & 511;
        int r0 = gbase + 2 * rp;
        hp[0][rp][k] = pack2f(hidden[r0 * Hn + k], hidden[(r0 + 1) * Hn + k]);
    }
    __syncthreads();

    for (int t = 0; t < Tn; t++) {
        const int cur = t & 1;

        // igate prefetch (independent of h -> overlaps the compute loop)
        const float ig0 = __ldcg(out + (size_t)b0       * (Tn * Hn) + (size_t)t * Hn + j);
        const float ig1 = __ldcg(out + (size_t)(b0 + 1) * (Tn * Hn) + (size_t)t * Hn + j);

        // ---- compute: partial dot over this thread's 128-k slice, 4 row-pairs ----
        ull a0 = 0, a1 = 0, a2 = 0, a3 = 0;
        const ulonglong2* h0q = (const ulonglong2*)(&hp[cur][0][rq * 128]);
        const ulonglong2* h1q = (const ulonglong2*)(&hp[cur][1][rq * 128]);
        const ulonglong2* h2q = (const ulonglong2*)(&hp[cur][2][rq * 128]);
        const ulonglong2* h3q = (const ulonglong2*)(&hp[cur][3][rq * 128]);
        #pragma unroll
        for (int u = 0; u < 32; u++) {
            float4 w = W4[u];
            ull wx = splat2f(w.x), wy = splat2f(w.y),
                wz = splat2f(w.z), ww = splat2f(w.w);
            ulonglong2 p0a = h0q[2*u], p0b = h0q[2*u+1];
            ffma2(a0, wx, p0a.x); ffma2(a0, wy, p0a.y);
            ffma2(a0, wz, p0b.x); ffma2(a0, ww, p0b.y);
            ulonglong2 p1a = h1q[2*u], p1b = h1q[2*u+1];
            ffma2(a1, wx, p1a.x); ffma2(a1, wy, p1a.y);
            ffma2(a1, wz, p1b.x); ffma2(a1, ww, p1b.y);
            ulonglong2 p2a = h2q[2*u], p2b = h2q[2*u+1];
            ffma2(a2, wx, p2a.x); ffma2(a2, wy, p2a.y);
            ffma2(a2, wz, p2b.x); ffma2(a2, ww, p2b.y);
            ulonglong2 p3a = h3q[2*u], p3b = h3q[2*u+1];
            ffma2(a3, wx, p3a.x); ffma2(a3, wy, p3a.y);
            ffma2(a3, wz, p3b.x); ffma2(a3, ww, p3b.y);
        }
        part[rq][0][jj] = a0;
        part[rq][1][jj] = a1;
        part[rq][2][jj] = a2;
        part[rq][3][jj] = a3;
        __syncthreads();

        // ---- epilogue: reduce k-slices, bias + ig + sigmoid, store, DSMEM push ----
        float2 p0 = unpack2f(part[0][rq][jj]);
        float2 p1 = unpack2f(part[1][rq][jj]);
        float2 p2 = unpack2f(part[2][rq][jj]);
        float2 p3 = unpack2f(part[3][rq][jj]);
        float zx = p0.x + p1.x + p2.x + p3.x + ig0 + bhj;
        float zy = p0.y + p1.y + p2.y + p3.y + ig1 + bhj;
        float h0v = sigmoidf_fast(zx);
        float h1v = sigmoidf_fast(zy);

        out[(size_t)b0       * (Tn * Hn) + (size_t)t * Hn + j] = h0v;
        out[(size_t)(b0 + 1) * (Tn * Hn) + (size_t)t * Hn + j] = h1v;
        if (t == Tn - 1) {
            hl[b0 * Hn + j]       = h0v;
            hl[(b0 + 1) * Hn + j] = h1v;
        }

        // Push packed pair into hp[cur^1] of every cluster CTA (incl. self)
        const ull v = pack2f(h0v, h1v);
        const int nb = cur ^ 1;
        #pragma unroll
        for (int r = 0; r < 8; r++) {
            asm volatile("st.shared::cluster.u64 [%0], %1;"
                         :: "r"(ra[nb][r]), "l"(v) : "memory");
        }

        // One barrier per step: release our DSMEM stores, acquire peers'.
        asm volatile("barrier.cluster.arrive.aligned;" ::: "memory");
        asm volatile("barrier.cluster.wait.aligned;"   ::: "memory");
    }
}

// ---------------------------------------------------------------------------
// Launch
// ---------------------------------------------------------------------------
extern "C" void kernel_launch(void* const* d_in, const int* in_sizes, int n_in,
                              void* d_out, int out_size)
{
    const float* x      = (const float*)d_in[0];   // [B, T, I]
    const float* hidden = (const float*)d_in[1];   // [B, H]
    const float* Wi     = (const float*)d_in[2];   // [H, I]
    const float* bi     = (const float*)d_in[3];   // [H]
    const float* Wh     = (const float*)d_in[4];   // [H, H]
    const float* bh     = (const float*)d_in[5];   // [H]
    float* out = (float*)d_out;                    // [B,T,H] output then [B,H] h_last

    dim3 g1(Hn / 64, (Bn * Tn) / 64);
    igates_kernel<<<g1, 256>>>(x, Wi, bi, out);

    rnn_kernel<<<128, 256>>>(out, hidden, Wh, bh);
}

// round 3
// speedup vs baseline: 1.1909x; 1.1909x over previous
#include <cuda_runtime.h>
#include <cstdint>

typedef unsigned long long ull;

constexpr int Bn = 128;
constexpr int Tn = 1024;
constexpr int In = 256;
constexpr int Hn = 512;
constexpr int NGROUP = 16;          // independent batch groups (8 rows each)
constexpr int NCTA_G = 8;           // CTAs per group (64 columns each)

// Packed h exchange buffers (ping-pong by t parity) + per-group counters.
__device__ ull      g_xchg[2][NGROUP][4 * 512];   // [buf][group][rp*512 + j]
__device__ unsigned g_cnt[NGROUP * 32];           // padded: one counter per 128B

__device__ __forceinline__ ull pack2f(float x, float y) {
    ull r; asm("mov.b64 %0, {%1, %2};" : "=l"(r) : "f"(x), "f"(y)); return r;
}
__device__ __forceinline__ float2 unpack2f(ull v) {
    float2 r; asm("mov.b64 {%0, %1}, %2;" : "=f"(r.x), "=f"(r.y) : "l"(v)); return r;
}
__device__ __forceinline__ ull splat2f(float x) {
    ull r; asm("mov.b64 %0, {%1, %1};" : "=l"(r) : "f"(x)); return r;
}
__device__ __forceinline__ void ffma2(ull& a, ull x, ull y) {
    asm("fma.rn.f32x2 %0, %1, %2, %0;" : "+l"(a) : "l"(x), "l"(y));
}
__device__ __forceinline__ float sigmoidf_fast(float z) {
    return __fdividef(1.0f, 1.0f + __expf(-z));
}

// ---------------------------------------------------------------------------
// Kernel 0: reset group counters (runs before rnn_kernel every launch)
// ---------------------------------------------------------------------------
__global__ void reset_kernel() {
    int i = threadIdx.x;
    if (i < NGROUP * 32) g_cnt[i] = 0u;
}

// ---------------------------------------------------------------------------
// Kernel 1: igates[m][n] = sum_k X[m][k] * Wi[n][k] + bi[n]   (R1 version)
// ---------------------------------------------------------------------------
__global__ __launch_bounds__(256) void igates_kernel(
    const float* __restrict__ X,
    const float* __restrict__ Wi,
    const float* __restrict__ bi,
    float* __restrict__ out)
{
    __shared__ float Xs[64][33];
    __shared__ float Ws[64][33];

    const int tid = threadIdx.x;
    const int tx = tid & 15;
    const int ty = tid >> 4;
    const int m0 = blockIdx.y * 64;
    const int n0 = blockIdx.x * 64;

    float acc[4][4] = {};

    for (int k0 = 0; k0 < In; k0 += 32) {
        #pragma unroll
        for (int hh = 0; hh < 2; hh++) {
            int idx = tid + 256 * hh;
            int r   = idx >> 3;
            int c4  = idx & 7;
            float4 v = *(const float4*)(X + (size_t)(m0 + r) * In + k0 + c4 * 4);
            Xs[r][c4*4+0] = v.x; Xs[r][c4*4+1] = v.y;
            Xs[r][c4*4+2] = v.z; Xs[r][c4*4+3] = v.w;
            float4 w = *(const float4*)(Wi + (size_t)(n0 + r) * In + k0 + c4 * 4);
            Ws[r][c4*4+0] = w.x; Ws[r][c4*4+1] = w.y;
            Ws[r][c4*4+2] = w.z; Ws[r][c4*4+3] = w.w;
        }
        __syncthreads();

        #pragma unroll
        for (int k = 0; k < 32; k++) {
            float a[4], b[4];
            #pragma unroll
            for (int i = 0; i < 4; i++) a[i] = Xs[ty*4 + i][k];
            #pragma unroll
            for (int j = 0; j < 4; j++) b[j] = Ws[tx*4 + j][k];
            #pragma unroll
            for (int i = 0; i < 4; i++)
                #pragma unroll
                for (int j = 0; j < 4; j++)
                    acc[i][j] += a[i] * b[j];
        }
        __syncthreads();
    }

    float4 bv = *(const float4*)(bi + n0 + tx * 4);
    #pragma unroll
    for (int i = 0; i < 4; i++) {
        float4 o = make_float4(acc[i][0] + bv.x, acc[i][1] + bv.y,
                               acc[i][2] + bv.z, acc[i][3] + bv.w);
        *(float4*)(out + (size_t)(m0 + ty*4 + i) * Hn + n0 + tx * 4) = o;
    }
}

// ---------------------------------------------------------------------------
// Kernel 2: persistent recurrence, counter-signaled L2 exchange.
//   128 CTAs = 16 groups x 8. Group g owns batch rows [8g,8g+8); CTA c owns
//   output columns [64c,64c+64). Per step each CTA:
//     spin (acquire) until all 8 group CTAs signaled step t-1
//     stage packed h (2048 ull) from g_xchg[(t-1)&1] into smem (4 LDG.128/thr)
//     compute its [8 x 64] slice: Wh in registers, fma.rn.f32x2, k-reduction
//       via shfl.bfly (k-slices mapped to lanes: rq = lane&3)
//     sigmoid, store to out[], store packed slice to g_xchg[t&1], then
//     __syncthreads + tid0 red.add.release signals step t.
//   Thread map: jj = (warp<<3)|(lane>>2)  (column), rq = lane&3 (k-slice /
//   epilogue row-pair). Smem h uses a 132-ull slice stride so the 4 distinct
//   per-warp LDS addresses are conflict-free.
// ---------------------------------------------------------------------------
__global__ __launch_bounds__(256, 1)
void rnn_kernel(
    float* __restrict__ out,
    const float* __restrict__ hidden,
    const float* __restrict__ Wh,
    const float* __restrict__ bh)
{
    __shared__ __align__(16) ull hp[4][532];    // [row-pair][rq*132 + k]

    const int tid   = threadIdx.x;
    const int lane  = tid & 31;
    const int warp  = tid >> 5;
    const int jj    = (warp << 3) | (lane >> 2);   // 0..63 column
    const int rq    = lane & 3;                    // k-slice & epilogue row-pair
    const int crank = blockIdx.x & 7;
    const int g     = blockIdx.x >> 3;
    const int gbase = g * 8;
    const int j     = crank * 64 + jj;
    const float bhj = bh[j];
    const int b0    = gbase + 2 * rq;

    float* __restrict__ hl = out + (size_t)Bn * Tn * Hn;
    unsigned* cnt = &g_cnt[g * 32];

    // Wh slice in registers: Wh[j][rq*128 .. +127]
    float4 W4[32];
    {
        const float4* wp = (const float4*)(Wh + (size_t)j * Hn + rq * 128);
        #pragma unroll
        for (int u = 0; u < 32; u++) W4[u] = wp[u];
    }

    // Stage initial hidden state into hp (scalar path, once)
    for (int i = tid; i < 2048; i += 256) {
        int rp = i >> 9, col = i & 511;
        int r0 = gbase + 2 * rp;
        hp[rp][(col >> 7) * 132 + (col & 127)] =
            pack2f(hidden[r0 * Hn + col], hidden[(r0 + 1) * Hn + col]);
    }
    __syncthreads();

    const size_t orow0 = (size_t)b0       * (Tn * Hn);
    const size_t orow1 = (size_t)(b0 + 1) * (Tn * Hn);

    // Precompute this thread's staging addresses
    const int sidx   = tid * 8;                    // 8 ull per thread
    const int s_rp   = sidx >> 9;
    const int s_col  = sidx & 511;
    ull* s_dst = &hp[s_rp][(s_col >> 7) * 132 + (s_col & 127)];

    for (int t = 0; t < Tn; t++) {
        // igate prefetch — depends only on igates kernel output, issue early
        const float ig0 = __ldcg(out + orow0 + (size_t)t * Hn + j);
        const float ig1 = __ldcg(out + orow1 + (size_t)t * Hn + j);

        if (t > 0) {
            // ---- wait for all 8 CTAs of the group to have signaled t-1 ----
            const unsigned target = 8u * (unsigned)t;
            unsigned c;
            do {
                asm volatile("ld.acquire.gpu.global.u32 %0, [%1];"
                             : "=r"(c) : "l"(cnt) : "memory");
            } while (c < target);

            // ---- stage packed h from the exchange buffer (4 LDG.128) ----
            const ulonglong2* src =
                (const ulonglong2*)(&g_xchg[(t - 1) & 1][g][sidx]);
            ulonglong2 v0 = src[0], v1 = src[1], v2 = src[2], v3 = src[3];
            ulonglong2* d2 = (ulonglong2*)s_dst;
            d2[0] = v0; d2[1] = v1; d2[2] = v2; d2[3] = v3;
            __syncthreads();
        }

        // ---- compute: 4 row-pairs over this thread's 128-k slice ----
        ull a0 = 0, a1 = 0, a2 = 0, a3 = 0;
        const ulonglong2* h0 = (const ulonglong2*)(&hp[0][rq * 132]);
        const ulonglong2* h1 = (const ulonglong2*)(&hp[1][rq * 132]);
        const ulonglong2* h2 = (const ulonglong2*)(&hp[2][rq * 132]);
        const ulonglong2* h3 = (const ulonglong2*)(&hp[3][rq * 132]);
        #pragma unroll
        for (int u = 0; u < 32; u++) {
            float4 w = W4[u];
            ull wx = splat2f(w.x), wy = splat2f(w.y),
                wz = splat2f(w.z), ww = splat2f(w.w);
            ulonglong2 p0a = h0[2*u], p0b = h0[2*u+1];
            ffma2(a0, wx, p0a.x); ffma2(a0, wy, p0a.y);
            ffma2(a0, wz, p0b.x); ffma2(a0, ww, p0b.y);
            ulonglong2 p1a = h1[2*u], p1b = h1[2*u+1];
            ffma2(a1, wx, p1a.x); ffma2(a1, wy, p1a.y);
            ffma2(a1, wz, p1b.x); ffma2(a1, ww, p1b.y);
            ulonglong2 p2a = h2[2*u], p2b = h2[2*u+1];
            ffma2(a2, wx, p2a.x); ffma2(a2, wy, p2a.y);
            ffma2(a2, wz, p2b.x); ffma2(a2, ww, p2b.y);
            ulonglong2 p3a = h3[2*u], p3b = h3[2*u+1];
            ffma2(a3, wx, p3a.x); ffma2(a3, wy, p3a.y);
            ffma2(a3, wz, p3b.x); ffma2(a3, ww, p3b.y);
        }

        // ---- k-slice reduction across the 4 lanes of each column group ----
        float2 z = make_float2(0.f, 0.f);
        {
            float2 v;
            v = unpack2f(a0);
            v.x += __shfl_xor_sync(0xffffffffu, v.x, 1);
            v.y += __shfl_xor_sync(0xffffffffu, v.y, 1);
            v.x += __shfl_xor_sync(0xffffffffu, v.x, 2);
            v.y += __shfl_xor_sync(0xffffffffu, v.y, 2);
            if (rq == 0) z = v;
            v = unpack2f(a1);
            v.x += __shfl_xor_sync(0xffffffffu, v.x, 1);
            v.y += __shfl_xor_sync(0xffffffffu, v.y, 1);
            v.x += __shfl_xor_sync(0xffffffffu, v.x, 2);
            v.y += __shfl_xor_sync(0xffffffffu, v.y, 2);
            if (rq == 1) z = v;
            v = unpack2f(a2);
            v.x += __shfl_xor_sync(0xffffffffu, v.x, 1);
            v.y += __shfl_xor_sync(0xffffffffu, v.y, 1);
            v.x += __shfl_xor_sync(0xffffffffu, v.x, 2);
            v.y += __shfl_xor_sync(0xffffffffu, v.y, 2);
            if (rq == 2) z = v;
            v = unpack2f(a3);
            v.x += __shfl_xor_sync(0xffffffffu, v.x, 1);
            v.y += __shfl_xor_sync(0xffffffffu, v.y, 1);
            v.x += __shfl_xor_sync(0xffffffffu, v.x, 2);
            v.y += __shfl_xor_sync(0xffffffffu, v.y, 2);
            if (rq == 3) z = v;
        }

        // ---- epilogue: bias + ig + sigmoid, store out + exchange, signal ----
        float h0v = sigmoidf_fast(z.x + ig0 + bhj);
        float h1v = sigmoidf_fast(z.y + ig1 + bhj);

        out[orow0 + (size_t)t * Hn + j] = h0v;
        out[orow1 + (size_t)t * Hn + j] = h1v;
        if (t == Tn - 1) {
            hl[b0 * Hn + j]       = h0v;
            hl[(b0 + 1) * Hn + j] = h1v;
        }
        g_xchg[t & 1][g][rq * 512 + j] = pack2f(h0v, h1v);

        __syncthreads();   // CTA-cumulative order: all stores precede the signal
        if (tid == 0) {
            asm volatile("red.add.release.gpu.global.u32 [%0], %1;"
                         :: "l"(cnt), "r"(1u) : "memory");
        }
    }
}

// ---------------------------------------------------------------------------
// Launch
// ---------------------------------------------------------------------------
extern "C" void kernel_launch(void* const* d_in, const int* in_sizes, int n_in,
                              void* d_out, int out_size)
{
    const float* x      = (const float*)d_in[0];   // [B, T, I]
    const float* hidden = (const float*)d_in[1];   // [B, H]
    const float* Wi     = (const float*)d_in[2];   // [H, I]
    const float* bi     = (const float*)d_in[3];   // [H]
    const float* Wh     = (const float*)d_in[4];   // [H, H]
    const float* bh     = (const float*)d_in[5];   // [H]
    float* out = (float*)d_out;                    // [B,T,H] output then [B,H] h_last

    dim3 g1(Hn / 64, (Bn * Tn) / 64);
    igates_kernel<<<g1, 256>>>(x, Wi, bi, out);

    reset_kernel<<<1, 512>>>();

    rnn_kernel<<<128, 256>>>(out, hidden, Wh, bh);
}

// round 5
// speedup vs baseline: 1.6353x; 1.3732x over previous
#include <cuda_runtime.h>
#include <cstdint>

typedef unsigned long long ull;

constexpr int Bn = 128;
constexpr int Tn = 1024;
constexpr int In = 256;
constexpr int Hn = 512;

// rnn smem layout (bytes)
constexpr int WS_BYTES  = 32 * 256 * 16;          // Wh smem half: [32][256] float4 = 131072
constexpr int HP_PAIR   = 520;                    // padded ull per (buf,pair)
constexpr int HP_BYTES  = 2 * 2 * HP_PAIR * 8;    // 16640
constexpr int MB_OFF    = WS_BYTES + HP_BYTES;    // mbar[2]
constexpr int SMEM_RNN  = MB_OFF + 16;

__device__ __forceinline__ ull pack2f(float x, float y) {
    ull r; asm("mov.b64 %0, {%1, %2};" : "=l"(r) : "f"(x), "f"(y)); return r;
}
__device__ __forceinline__ float2 unpack2f(ull v) {
    float2 r; asm("mov.b64 {%0, %1}, %2;" : "=f"(r.x), "=f"(r.y) : "l"(v)); return r;
}
__device__ __forceinline__ ull splat2f(float x) {
    ull r; asm("mov.b64 %0, {%1, %1};" : "=l"(r) : "f"(x)); return r;
}
__device__ __forceinline__ void ffma2(ull& a, ull x, ull y) {
    asm("fma.rn.f32x2 %0, %1, %2, %0;" : "+l"(a) : "l"(x), "l"(y));
}
__device__ __forceinline__ float sigmoidf_fast(float z) {
    return __fdividef(1.0f, 1.0f + __expf(-z));
}
__device__ __forceinline__ uint32_t smem_u32(const void* p) {
    return (uint32_t)__cvta_generic_to_shared(p);
}

// ---------------------------------------------------------------------------
// Kernel 1: igates = x @ Wi^T + bi  (f32x2 version, measured 777us)
// ---------------------------------------------------------------------------
__global__ __launch_bounds__(256) void igates_kernel(
    const float* __restrict__ X,
    const float* __restrict__ Wi,
    const float* __restrict__ bi,
    float* __restrict__ out)
{
    __shared__ __align__(16) float Xs[32][68];   // [k][m]
    __shared__ __align__(16) float Ws[32][68];   // [k][n]

    const int tid = threadIdx.x;
    const int tx = tid & 15;
    const int ty = tid >> 4;
    const int m0 = blockIdx.y * 64;
    const int n0 = blockIdx.x * 64;

    ull acc[4][2] = {};

    for (int k0 = 0; k0 < In; k0 += 32) {
        #pragma unroll
        for (int hh = 0; hh < 2; hh++) {
            int idx = tid + 256 * hh;
            int r   = idx >> 3;
            int c4  = idx & 7;
            float4 v = *(const float4*)(X + (size_t)(m0 + r) * In + k0 + c4 * 4);
            Xs[c4*4+0][r] = v.x; Xs[c4*4+1][r] = v.y;
            Xs[c4*4+2][r] = v.z; Xs[c4*4+3][r] = v.w;
            float4 w = *(const float4*)(Wi + (size_t)(n0 + r) * In + k0 + c4 * 4);
            Ws[c4*4+0][r] = w.x; Ws[c4*4+1][r] = w.y;
            Ws[c4*4+2][r] = w.z; Ws[c4*4+3][r] = w.w;
        }
        __syncthreads();

        #pragma unroll
        for (int k = 0; k < 32; k++) {
            float4 a4 = *(const float4*)(&Xs[k][ty * 4]);
            const ull* b2 = (const ull*)(&Ws[k][tx * 4]);
            ull bp0 = b2[0], bp1 = b2[1];
            ull s0 = splat2f(a4.x), s1 = splat2f(a4.y),
                s2 = splat2f(a4.z), s3 = splat2f(a4.w);
            ffma2(acc[0][0], s0, bp0); ffma2(acc[0][1], s0, bp1);
            ffma2(acc[1][0], s1, bp0); ffma2(acc[1][1], s1, bp1);
            ffma2(acc[2][0], s2, bp0); ffma2(acc[2][1], s2, bp1);
            ffma2(acc[3][0], s3, bp0); ffma2(acc[3][1], s3, bp1);
        }
        __syncthreads();
    }

    float4 bv = *(const float4*)(bi + n0 + tx * 4);
    #pragma unroll
    for (int i = 0; i < 4; i++) {
        float2 lo = unpack2f(acc[i][0]);
        float2 hi = unpack2f(acc[i][1]);
        float4 o = make_float4(lo.x + bv.x, lo.y + bv.y, hi.x + bv.z, hi.y + bv.w);
        *(float4*)(out + (size_t)(m0 + ty*4 + i) * Hn + n0 + tx * 4) = o;
    }
}

// ---------------------------------------------------------------------------
// Kernel 2: recurrence, 32 clusters x 4 CTAs, DSMEM h-exchange + mbarriers.
//   (R4 design; fix = trailing cluster barrier so no CTA exits while peers'
//   st.shared::cluster / mbarrier.arrive into its SMEM are in flight.)
// ---------------------------------------------------------------------------
__global__ __launch_bounds__(256, 1) __cluster_dims__(4, 1, 1)
void rnn_kernel(
    float* __restrict__ out,
    const float* __restrict__ hidden,
    const float* __restrict__ Wh,
    const float* __restrict__ bh)
{
    extern __shared__ char sm[];
    float4* Wsm   = (float4*)sm;                 // [32][256]
    ull*    hpb   = (ull*)(sm + WS_BYTES);       // [2 buf][2 pair][520]
    ull*    mbar  = (ull*)(sm + MB_OFF);         // [2]

    const int tid  = threadIdx.x;
    const int lane = tid & 31;
    const int warp = tid >> 5;
    const int jj   = (warp << 4) | (lane >> 1);  // 0..127 column in slice
    const int rq   = lane & 1;                   // k-half / epilogue row-pair
    uint32_t crank; asm("mov.u32 %0, %%cluster_ctarank;" : "=r"(crank));
    const int g    = blockIdx.x >> 2;
    const int j    = (int)crank * 128 + jj;      // global column
    const float bhj = bh[j];
    const int b0   = 4 * g + 2 * rq;             // epilogue rows (b0, b0+1)
    const int jidx = j + ((j >> 8) << 3);        // padded column index

    float* __restrict__ hl = out + (size_t)Bn * Tn * Hn;

    // ---- Wh slice: k in [256*rq, 256*rq+256); first 128 -> regs, rest -> smem
    float4 W4[32];
    {
        const float4* wp = (const float4*)(Wh + (size_t)j * Hn + 256 * rq);
        #pragma unroll
        for (int u = 0; u < 32; u++) W4[u] = wp[u];
        const float4* wq = (const float4*)(Wh + (size_t)j * Hn + 256 * rq + 128);
        #pragma unroll
        for (int u = 0; u < 32; u++) Wsm[u * 256 + tid] = wq[u];
    }

    // ---- mbarrier init (count = 32 warp-arrivals: 8 warps x 4 CTAs) ----
    if (tid == 0) {
        uint32_t m0 = smem_u32(&mbar[0]), m1 = smem_u32(&mbar[1]);
        asm volatile("mbarrier.init.shared.b64 [%0], %1;" :: "r"(m0), "r"(32u) : "memory");
        asm volatile("mbarrier.init.shared.b64 [%0], %1;" :: "r"(m1), "r"(32u) : "memory");
    }

    // ---- stage initial hidden into hp buf 0 (all 4 group rows, locally) ----
    for (int i = tid; i < 1024; i += 256) {
        int pair = i >> 9, col = i & 511;
        int idx  = col + ((col >> 8) << 3);
        hpb[pair * HP_PAIR + idx] =
            pack2f(hidden[(4 * g + 2 * pair) * Hn + col],
                   hidden[(4 * g + 2 * pair + 1) * Hn + col]);
    }
    __syncthreads();

    // cluster-wide: mbar init + staging complete before any remote store/arrive
    asm volatile("barrier.cluster.arrive.aligned;" ::: "memory");
    asm volatile("barrier.cluster.wait.aligned;"   ::: "memory");

    // ---- precompute remote addresses ----
    uint32_t hp_u32 = smem_u32(hpb);
    uint32_t mb_u32 = smem_u32(mbar);
    uint32_t rhp[4], rmb[4];
    #pragma unroll
    for (int r = 0; r < 4; r++) {
        asm("mapa.shared::cluster.u32 %0, %1, %2;" : "=r"(rhp[r]) : "r"(hp_u32), "r"(r));
        asm("mapa.shared::cluster.u32 %0, %1, %2;" : "=r"(rmb[r]) : "r"(mb_u32), "r"(r));
    }
    const uint32_t poff = (uint32_t)(rq * HP_PAIR + jidx) * 8u;

    const size_t orow0 = (size_t)b0       * (Tn * Hn);
    const size_t orow1 = (size_t)(b0 + 1) * (Tn * Hn);

    for (int t = 0; t < Tn; t++) {
        const int cur = t & 1;
        const int nb  = cur ^ 1;

        // igate prefetch (independent of h)
        const float ig0 = __ldcg(out + orow0 + (size_t)t * Hn + j);
        const float ig1 = __ldcg(out + orow1 + (size_t)t * Hn + j);

        if (t > 0) {
            const uint32_t maddr = smem_u32(&mbar[cur]);
            const uint32_t phase = (uint32_t)((t - 1) >> 1) & 1u;
            uint32_t done;
            do {
                asm volatile(
                    "{\n\t.reg .pred p;\n\t"
                    "mbarrier.try_wait.parity.acquire.cluster.shared::cta.b64 p, [%1], %2, 0x989680;\n\t"
                    "selp.b32 %0, 1, 0, p;\n\t}"
                    : "=r"(done) : "r"(maddr), "r"(phase) : "memory");
            } while (!done);
        }

        // ---- compute: 2 row-pairs over this thread's 256-k slice ----
        const ull* hp0 = hpb + cur * (2 * HP_PAIR) + 0 * HP_PAIR + 264 * rq;
        const ull* hp1 = hpb + cur * (2 * HP_PAIR) + 1 * HP_PAIR + 264 * rq;
        ull a00 = 0, a01 = 0, a10 = 0, a11 = 0;
        #pragma unroll
        for (int u = 0; u < 32; u++) {
            float4 w = W4[u];
            ull wx = splat2f(w.x), wy = splat2f(w.y),
                wz = splat2f(w.z), ww = splat2f(w.w);
            ulonglong2 h0a = *(const ulonglong2*)(hp0 + 4*u);
            ulonglong2 h0b = *(const ulonglong2*)(hp0 + 4*u + 2);
            ffma2(a00, wx, h0a.x); ffma2(a01, wy, h0a.y);
            ffma2(a00, wz, h0b.x); ffma2(a01, ww, h0b.y);
            ulonglong2 h1a = *(const ulonglong2*)(hp1 + 4*u);
            ulonglong2 h1b = *(const ulonglong2*)(hp1 + 4*u + 2);
            ffma2(a10, wx, h1a.x); ffma2(a11, wy, h1a.y);
            ffma2(a10, wz, h1b.x); ffma2(a11, ww, h1b.y);
        }
        #pragma unroll
        for (int u = 0; u < 32; u++) {
            float4 w = Wsm[u * 256 + tid];
            ull wx = splat2f(w.x), wy = splat2f(w.y),
                wz = splat2f(w.z), ww = splat2f(w.w);
            ulonglong2 h0a = *(const ulonglong2*)(hp0 + 128 + 4*u);
            ulonglong2 h0b = *(const ulonglong2*)(hp0 + 128 + 4*u + 2);
            ffma2(a00, wx, h0a.x); ffma2(a01, wy, h0a.y);
            ffma2(a00, wz, h0b.x); ffma2(a01, ww, h0b.y);
            ulonglong2 h1a = *(const ulonglong2*)(hp1 + 128 + 4*u);
            ulonglong2 h1b = *(const ulonglong2*)(hp1 + 128 + 4*u + 2);
            ffma2(a10, wx, h1a.x); ffma2(a11, wy, h1a.y);
            ffma2(a10, wz, h1b.x); ffma2(a11, ww, h1b.y);
        }

        // ---- k-half reduction across lane pairs (xor 1) ----
        float2 s0 = unpack2f(a00), s0b = unpack2f(a01);
        float2 s1 = unpack2f(a10), s1b = unpack2f(a11);
        float p0x = s0.x + s0b.x, p0y = s0.y + s0b.y;
        float p1x = s1.x + s1b.x, p1y = s1.y + s1b.y;
        p0x += __shfl_xor_sync(0xffffffffu, p0x, 1);
        p0y += __shfl_xor_sync(0xffffffffu, p0y, 1);
        p1x += __shfl_xor_sync(0xffffffffu, p1x, 1);
        p1y += __shfl_xor_sync(0xffffffffu, p1y, 1);
        const float zx = (rq ? p1x : p0x) + ig0 + bhj;
        const float zy = (rq ? p1y : p0y) + ig1 + bhj;
        float h0v = sigmoidf_fast(zx);
        float h1v = sigmoidf_fast(zy);

        // ---- stores: output + DSMEM push to all 4 CTAs' hp[nb] ----
        out[orow0 + (size_t)t * Hn + j] = h0v;
        out[orow1 + (size_t)t * Hn + j] = h1v;
        if (t == Tn - 1) {
            hl[b0 * Hn + j]       = h0v;
            hl[(b0 + 1) * Hn + j] = h1v;
        }
        const ull v = pack2f(h0v, h1v);
        const uint32_t boff = (uint32_t)(nb * 2 * HP_PAIR) * 8u + poff;
        #pragma unroll
        for (int r = 0; r < 4; r++) {
            asm volatile("st.shared::cluster.u64 [%0], %1;"
                         :: "r"(rhp[r] + boff), "l"(v) : "memory");
        }

        // ---- per-warp arrival on all 4 CTAs' mbar[nb] ----
        __syncwarp();
        if (lane == 0) {
            const uint32_t moff = (uint32_t)nb * 8u;
            #pragma unroll
            for (int r = 0; r < 4; r++) {
                asm volatile("mbarrier.arrive.release.cluster.shared::cluster.b64 _, [%0];"
                             :: "r"(rmb[r] + moff) : "memory");
            }
        }
    }

    // ---- REQUIRED: no CTA may exit while peers' DSMEM stores / mbarrier
    // arrivals targeting its SMEM are still in flight. ----
    asm volatile("barrier.cluster.arrive.aligned;" ::: "memory");
    asm volatile("barrier.cluster.wait.aligned;"   ::: "memory");
}

// ---------------------------------------------------------------------------
// Launch
// ---------------------------------------------------------------------------
extern "C" void kernel_launch(void* const* d_in, const int* in_sizes, int n_in,
                              void* d_out, int out_size)
{
    const float* x      = (const float*)d_in[0];   // [B, T, I]
    const float* hidden = (const float*)d_in[1];   // [B, H]
    const float* Wi     = (const float*)d_in[2];   // [H, I]
    const float* bi     = (const float*)d_in[3];   // [H]
    const float* Wh     = (const float*)d_in[4];   // [H, H]
    const float* bh     = (const float*)d_in[5];   // [H]
    float* out = (float*)d_out;                    // [B,T,H] then [B,H] h_last

    dim3 g1(Hn / 64, (Bn * Tn) / 64);
    igates_kernel<<<g1, 256>>>(x, Wi, bi, out);

    static bool attr_set = false;
    if (!attr_set) {
        cudaFuncSetAttribute(rnn_kernel,
                             cudaFuncAttributeMaxDynamicSharedMemorySize, SMEM_RNN);
        attr_set = true;
    }
    rnn_kernel<<<128, 256, SMEM_RNN>>>(out, hidden, Wh, bh);
}